// round 1
// baseline (speedup 1.0000x reference)
#include <cuda_runtime.h>
#include <float.h>
#include <math.h>

// Problem shape (fixed for this problem instance)
#define B_   2
#define NQ   2048
#define NKV  2048
#define C_   1024
#define H_   16
#define HD   64
#define M_   (B_*NQ)   // 4096 rows for all projection GEMMs

// Scratch (allocation-free: device globals)
__device__ float g_Q[B_*H_*NQ*HD];   // [B,H,L,hd] after projection+rope
__device__ float g_K[B_*H_*NKV*HD];
__device__ float g_V[B_*H_*NKV*HD];
__device__ float g_X[B_*NQ*C_];      // attention output, [B,N,C]

// ---------------------------------------------------------------------------
// Tiled SGEMM: out[M,N] = A[M,K] @ W[K,N]
// EPI=0: plain row-major write. EPI=1: head-split write to [B,H,L,hd].
// Requires M%128==0, N%128==0, K%16==0 (true here: 4096/1024/1024).
// ---------------------------------------------------------------------------
template<int EPI>
__global__ __launch_bounds__(256)
void gemm128(const float* __restrict__ A, const float* __restrict__ W,
             float* __restrict__ out, int M, int N, int K, int L)
{
    __shared__ float As[16][128];   // As[k][m] (transposed A tile)
    __shared__ float Bs[16][128];   // Bs[k][n]

    const int tid = threadIdx.x;
    const int tx  = tid & 15;       // 0..15 -> 8 output cols each
    const int ty  = tid >> 4;       // 0..15 -> 8 output rows each
    const int m0  = blockIdx.y * 128;
    const int n0  = blockIdx.x * 128;

    float acc[8][8];
    #pragma unroll
    for (int i = 0; i < 8; i++)
        #pragma unroll
        for (int j = 0; j < 8; j++) acc[i][j] = 0.f;

    for (int k0 = 0; k0 < K; k0 += 16) {
        // Load A tile 128x16 (512 float4) and B tile 16x128 (512 float4)
        #pragma unroll
        for (int it = 0; it < 2; it++) {
            int idx = tid + it * 256;
            int row = idx >> 2, kq = idx & 3;
            float4 av = *(const float4*)(A + (size_t)(m0 + row) * K + k0 + kq * 4);
            As[kq*4+0][row] = av.x; As[kq*4+1][row] = av.y;
            As[kq*4+2][row] = av.z; As[kq*4+3][row] = av.w;
            int kr = idx >> 5, nq = idx & 31;
            *(float4*)(&Bs[kr][nq*4]) =
                *(const float4*)(W + (size_t)(k0 + kr) * N + n0 + nq * 4);
        }
        __syncthreads();

        #pragma unroll
        for (int kk = 0; kk < 16; kk++) {
            float ra[8], rb[8];
            *(float4*)(ra)     = *(const float4*)(&As[kk][ty*8]);
            *(float4*)(ra + 4) = *(const float4*)(&As[kk][ty*8 + 4]);
            *(float4*)(rb)     = *(const float4*)(&Bs[kk][tx*8]);
            *(float4*)(rb + 4) = *(const float4*)(&Bs[kk][tx*8 + 4]);
            #pragma unroll
            for (int i = 0; i < 8; i++)
                #pragma unroll
                for (int j = 0; j < 8; j++)
                    acc[i][j] = fmaf(ra[i], rb[j], acc[i][j]);
        }
        __syncthreads();
    }

    #pragma unroll
    for (int i = 0; i < 8; i++) {
        int m = m0 + ty * 8 + i;
        if (EPI == 0) {
            float* o = out + (size_t)m * N + n0 + tx * 8;
            *(float4*)(o)     = *(float4*)(&acc[i][0]);
            *(float4*)(o + 4) = *(float4*)(&acc[i][4]);
        } else {
            int b = m / L, l = m % L;
            #pragma unroll
            for (int j = 0; j < 8; j++) {
                int n = n0 + tx * 8 + j;
                int h = n >> 6, d = n & 63;
                out[(((size_t)(b * H_ + h) * L + l) << 6) + d] = acc[i][j];
            }
        }
    }
}

// ---------------------------------------------------------------------------
// In-place RoPE on [B,H,L,hd] tensor. One thread per (row, pair) where
// pair d in [0,32): out[d]    = s*(x[d]*cos(p[d])    - x[d+32]*sin(p[d]))
//                   out[d+32] = s*(x[d+32]*cos(p[d+32]) + x[d]*sin(p[d+32]))
// ---------------------------------------------------------------------------
__global__ __launch_bounds__(256)
void rope_kernel(float* __restrict__ t, const float* __restrict__ pos,
                 float scale, int L)
{
    int idx  = blockIdx.x * blockDim.x + threadIdx.x;
    int pair = idx & 31;
    int row  = idx >> 5;              // over B*H*L rows
    int l    = row & (L - 1);         // L is a power of two (2048)
    float* p = t + (size_t)row * 64;
    float x1 = p[pair], x2 = p[pair + 32];
    float th1 = pos[l * 64 + pair];
    float th2 = pos[l * 64 + pair + 32];
    float s1, c1, s2, c2;
    sincosf(th1, &s1, &c1);
    sincosf(th2, &s2, &c2);
    p[pair]      = scale * (x1 * c1 - x2 * s1);
    p[pair + 32] = scale * (x2 * c2 + x1 * s2);
}

// ---------------------------------------------------------------------------
// Flash-style attention. Block = one (b,h) head x 64 query rows.
// 256 threads; each owns 2 query rows x 8 head-dims. Streaming softmax with
// exact -FLT_MAX masking (matches reference even for fully-masked rows).
// Dynamic smem: Qs/Ks/Vs/Ps, each [64][65] floats.
// ---------------------------------------------------------------------------
__global__ __launch_bounds__(256)
void attn_kernel(const int* __restrict__ mask, float* __restrict__ X)
{
    extern __shared__ float sm[];
    float (*Qs)[65] = (float(*)[65])(sm);
    float (*Ks)[65] = (float(*)[65])(sm + 64 * 65);
    float (*Vs)[65] = (float(*)[65])(sm + 2 * 64 * 65);
    float (*Ps)[65] = (float(*)[65])(sm + 3 * 64 * 65);
    __shared__ int maskS[64];

    const int tid = threadIdx.x;
    const int bh  = blockIdx.x;       // b*16+h
    const int b   = bh >> 4;
    const int h   = bh & 15;
    const int q0  = blockIdx.y * 64;
    const int i0  = (tid >> 3) * 2;   // first of 2 owned query rows
    const int i1  = i0 + 1;
    const int c0  = (tid & 7) * 8;    // first of 8 owned cols

    // Load Q tile [64][64]
    const float* Qg = g_Q + ((size_t)bh * NQ + q0) * HD;
    for (int i4 = tid; i4 < 1024; i4 += 256) {
        float4 qv = ((const float4*)Qg)[i4];
        int r = i4 >> 4, c = (i4 & 15) * 4;
        Qs[r][c] = qv.x; Qs[r][c+1] = qv.y; Qs[r][c+2] = qv.z; Qs[r][c+3] = qv.w;
    }

    float m0v = -INFINITY, m1v = -INFINITY, l0v = 0.f, l1v = 0.f;
    float acc0[8], acc1[8];
    #pragma unroll
    for (int d = 0; d < 8; d++) { acc0[d] = 0.f; acc1[d] = 0.f; }

    for (int j0 = 0; j0 < NKV; j0 += 64) {
        __syncthreads();   // protects Ks/Vs/Ps/maskS (and Q load on iter 0)
        const float* Kg = g_K + ((size_t)bh * NKV + j0) * HD;
        const float* Vg = g_V + ((size_t)bh * NKV + j0) * HD;
        for (int i4 = tid; i4 < 1024; i4 += 256) {
            float4 kv = ((const float4*)Kg)[i4];
            int r = i4 >> 4, c = (i4 & 15) * 4;
            Ks[r][c] = kv.x; Ks[r][c+1] = kv.y; Ks[r][c+2] = kv.z; Ks[r][c+3] = kv.w;
            float4 vv = ((const float4*)Vg)[i4];
            Vs[r][c] = vv.x; Vs[r][c+1] = vv.y; Vs[r][c+2] = vv.z; Vs[r][c+3] = vv.w;
        }
        if (tid < 64) maskS[tid] = mask[b * NKV + j0 + tid];
        __syncthreads();

        // S = Q @ K^T for this tile (2 rows x 8 cols per thread)
        float s0[8], s1[8];
        #pragma unroll
        for (int jj = 0; jj < 8; jj++) { s0[jj] = 0.f; s1[jj] = 0.f; }
        #pragma unroll 4
        for (int dd = 0; dd < 64; dd++) {
            float qa = Qs[i0][dd], qb = Qs[i1][dd];
            #pragma unroll
            for (int jj = 0; jj < 8; jj++) {
                float kv = Ks[c0 + jj][dd];
                s0[jj] = fmaf(qa, kv, s0[jj]);
                s1[jj] = fmaf(qb, kv, s1[jj]);
            }
        }

        // Mask + tile row max
        float mt0 = -FLT_MAX, mt1 = -FLT_MAX;
        #pragma unroll
        for (int jj = 0; jj < 8; jj++) {
            if (maskS[c0 + jj] == 0) { s0[jj] = -FLT_MAX; s1[jj] = -FLT_MAX; }
            mt0 = fmaxf(mt0, s0[jj]); mt1 = fmaxf(mt1, s1[jj]);
        }
        #pragma unroll
        for (int o = 4; o >= 1; o >>= 1) {
            mt0 = fmaxf(mt0, __shfl_xor_sync(0xffffffffu, mt0, o));
            mt1 = fmaxf(mt1, __shfl_xor_sync(0xffffffffu, mt1, o));
        }
        float nm0 = fmaxf(m0v, mt0), nm1 = fmaxf(m1v, mt1);
        float a0 = __expf(m0v - nm0), a1 = __expf(m1v - nm1);

        float ls0 = 0.f, ls1 = 0.f;
        #pragma unroll
        for (int jj = 0; jj < 8; jj++) {
            float p0 = __expf(s0[jj] - nm0);
            float p1 = __expf(s1[jj] - nm1);
            Ps[i0][c0 + jj] = p0; Ps[i1][c0 + jj] = p1;
            ls0 += p0; ls1 += p1;
        }
        #pragma unroll
        for (int o = 4; o >= 1; o >>= 1) {
            ls0 += __shfl_xor_sync(0xffffffffu, ls0, o);
            ls1 += __shfl_xor_sync(0xffffffffu, ls1, o);
        }
        l0v = l0v * a0 + ls0;
        l1v = l1v * a1 + ls1;
        m0v = nm0; m1v = nm1;
        #pragma unroll
        for (int d = 0; d < 8; d++) { acc0[d] *= a0; acc1[d] *= a1; }
        __syncthreads();

        // O += P @ V
        #pragma unroll 4
        for (int j = 0; j < 64; j++) {
            float pa = Ps[i0][j], pb = Ps[i1][j];
            #pragma unroll
            for (int d = 0; d < 8; d++) {
                float vv = Vs[j][c0 + d];
                acc0[d] = fmaf(pa, vv, acc0[d]);
                acc1[d] = fmaf(pb, vv, acc1[d]);
            }
        }
    }

    float inv0 = 1.f / l0v, inv1 = 1.f / l1v;
    float* x0 = X + ((size_t)(b * NQ + q0 + i0) * C_) + h * HD + c0;
    float* x1 = X + ((size_t)(b * NQ + q0 + i1) * C_) + h * HD + c0;
    #pragma unroll
    for (int d = 0; d < 8; d++) { x0[d] = acc0[d] * inv0; x1[d] = acc1[d] * inv1; }
}

// ---------------------------------------------------------------------------
// Launch. Inputs (metadata order): q,k,v,mask,pos_emb,qW,kW,vW,projW.
// ---------------------------------------------------------------------------
extern "C" void kernel_launch(void* const* d_in, const int* in_sizes, int n_in,
                              void* d_out, int out_size)
{
    const float* q    = (const float*)d_in[0];
    const float* k    = (const float*)d_in[1];
    const float* v    = (const float*)d_in[2];
    const int*   mask = (const int*)  d_in[3];   // nonzero test: works for i32 or f32 bool encoding
    const float* pos  = (const float*)d_in[4];
    const float* qW   = (const float*)d_in[5];
    const float* kW   = (const float*)d_in[6];
    const float* vW   = (const float*)d_in[7];
    const float* pW   = (const float*)d_in[8];
    float* out = (float*)d_out;

    float *Qp, *Kp, *Vp, *Xp;
    cudaGetSymbolAddress((void**)&Qp, g_Q);
    cudaGetSymbolAddress((void**)&Kp, g_K);
    cudaGetSymbolAddress((void**)&Vp, g_V);
    cudaGetSymbolAddress((void**)&Xp, g_X);

    const int SMEM_ATT = 4 * 64 * 65 * (int)sizeof(float);   // 66560 B
    cudaFuncSetAttribute(attn_kernel, cudaFuncAttributeMaxDynamicSharedMemorySize, SMEM_ATT);

    dim3 gg(C_ / 128, M_ / 128);   // (8, 32)
    gemm128<1><<<gg, 256>>>(q, qW, Qp, M_, C_, C_, NQ);
    gemm128<1><<<gg, 256>>>(k, kW, Kp, M_, C_, C_, NKV);
    gemm128<1><<<gg, 256>>>(v, vW, Vp, M_, C_, C_, NKV);

    int ropeBlocks = (B_ * H_ * NQ * 32) / 256;   // 8192
    rope_kernel<<<ropeBlocks, 256>>>(Qp, pos, 0.125f, NQ);    // scale = hd^-0.5 = 1/8
    rope_kernel<<<ropeBlocks, 256>>>(Kp, pos, 1.0f, NKV);

    attn_kernel<<<dim3(B_ * H_, NQ / 64), 256, SMEM_ATT>>>(mask, Xp);

    gemm128<0><<<gg, 256>>>(Xp, pW, out, M_, C_, C_, NQ);
}

// round 2
// speedup vs baseline: 1.1001x; 1.1001x over previous
#include <cuda_runtime.h>
#include <float.h>
#include <math.h>

// Problem shape (fixed)
#define B_   2
#define NQ   2048
#define NKV  2048
#define C_   1024
#define H_   16
#define HD   64
#define M_   (B_*NQ)   // 4096

typedef unsigned long long u64;

// ---- packed f32x2 helpers (sm_103a FFMA2 path) ------------------------------
__device__ __forceinline__ u64 pack2(float lo, float hi) {
    u64 r; asm("mov.b64 %0, {%1,%2};" : "=l"(r) : "f"(lo), "f"(hi)); return r;
}
__device__ __forceinline__ u64 dup2(float x) { return pack2(x, x); }
__device__ __forceinline__ void unpack2(u64 v, float& lo, float& hi) {
    asm("mov.b64 {%0,%1}, %2;" : "=f"(lo), "=f"(hi) : "l"(v));
}
__device__ __forceinline__ void ffma2(u64& d, u64 a, u64 b) {
    asm("fma.rn.f32x2 %0, %1, %2, %3;" : "=l"(d) : "l"(a), "l"(b), "l"(d));
}
__device__ __forceinline__ void fmul2(u64& d, u64 a, u64 b) {
    asm("mul.rn.f32x2 %0, %1, %2;" : "=l"(d) : "l"(a), "l"(b));
}

// Scratch (allocation-free: device globals)
__device__ float g_Q[B_*H_*NQ*HD];
__device__ float g_K[B_*H_*NKV*HD];
__device__ float g_V[B_*H_*NKV*HD];
__device__ float g_X[B_*NQ*C_];

// ---------------------------------------------------------------------------
// Tiled SGEMM body: out[M,N] = A[M,K] @ W[K,N], FFMA2 inner loop.
// EPI=0: row-major write. EPI=1: head-split write to [B,H,L,hd].
// ---------------------------------------------------------------------------
template<int EPI>
__device__ __forceinline__
void gemm_body(const float* __restrict__ A, const float* __restrict__ W,
               float* __restrict__ out, int M, int N, int K, int L)
{
    __shared__ float As[16][128];   // As[k][m]
    __shared__ float Bs[16][128];   // Bs[k][n]

    const int tid = threadIdx.x;
    const int tx  = tid & 15;
    const int ty  = tid >> 4;
    const int m0  = blockIdx.y * 128;
    const int n0  = blockIdx.x * 128;

    u64 acc[8][4];
    #pragma unroll
    for (int i = 0; i < 8; i++)
        #pragma unroll
        for (int p = 0; p < 4; p++) acc[i][p] = 0ull;

    for (int k0 = 0; k0 < K; k0 += 16) {
        #pragma unroll
        for (int it = 0; it < 2; it++) {
            int idx = tid + it * 256;
            int row = idx >> 2, kq = idx & 3;
            float4 av = *(const float4*)(A + (size_t)(m0 + row) * K + k0 + kq * 4);
            As[kq*4+0][row] = av.x; As[kq*4+1][row] = av.y;
            As[kq*4+2][row] = av.z; As[kq*4+3][row] = av.w;
            int kr = idx >> 5, nq = idx & 31;
            *(float4*)(&Bs[kr][nq*4]) =
                *(const float4*)(W + (size_t)(k0 + kr) * N + n0 + nq * 4);
        }
        __syncthreads();

        #pragma unroll
        for (int kk = 0; kk < 16; kk++) {
            float ra[8];
            *(float4*)(ra)     = *(const float4*)(&As[kk][ty*8]);
            *(float4*)(ra + 4) = *(const float4*)(&As[kk][ty*8 + 4]);
            u64 rb[4];
            const u64* bp = (const u64*)(&Bs[kk][tx*8]);
            rb[0] = bp[0]; rb[1] = bp[1]; rb[2] = bp[2]; rb[3] = bp[3];
            #pragma unroll
            for (int i = 0; i < 8; i++) {
                u64 ad = dup2(ra[i]);
                #pragma unroll
                for (int p = 0; p < 4; p++) ffma2(acc[i][p], ad, rb[p]);
            }
        }
        __syncthreads();
    }

    #pragma unroll
    for (int i = 0; i < 8; i++) {
        int m = m0 + ty * 8 + i;
        float v[8];
        #pragma unroll
        for (int p = 0; p < 4; p++) unpack2(acc[i][p], v[2*p], v[2*p+1]);
        if (EPI == 0) {
            float* o = out + (size_t)m * N + n0 + tx * 8;
            *(float4*)(o)     = make_float4(v[0], v[1], v[2], v[3]);
            *(float4*)(o + 4) = make_float4(v[4], v[5], v[6], v[7]);
        } else {
            int b = m / L, l = m % L;
            #pragma unroll
            for (int j = 0; j < 8; j++) {
                int n = n0 + tx * 8 + j;
                int h = n >> 6, d = n & 63;
                out[(((size_t)(b * H_ + h) * L + l) << 6) + d] = v[j];
            }
        }
    }
}

// Fused q/k/v projection: blockIdx.z picks the GEMM (768 blocks total)
__global__ __launch_bounds__(256)
void gemm_proj(const float* __restrict__ q, const float* __restrict__ k,
               const float* __restrict__ v,
               const float* __restrict__ qW, const float* __restrict__ kW,
               const float* __restrict__ vW,
               float* __restrict__ Q, float* __restrict__ K, float* __restrict__ V)
{
    int z = blockIdx.z;
    const float* A = (z == 0) ? q  : (z == 1) ? k  : v;
    const float* W = (z == 0) ? qW : (z == 1) ? kW : vW;
    float* O       = (z == 0) ? Q  : (z == 1) ? K  : V;
    gemm_body<1>(A, W, O, M_, C_, C_, NQ);
}

__global__ __launch_bounds__(256)
void gemm_out(const float* __restrict__ A, const float* __restrict__ W,
              float* __restrict__ out)
{
    gemm_body<0>(A, W, out, M_, C_, C_, NQ);
}

// ---------------------------------------------------------------------------
// In-place RoPE on [B,H,L,hd]
// ---------------------------------------------------------------------------
__global__ __launch_bounds__(256)
void rope_kernel(float* __restrict__ t, const float* __restrict__ pos,
                 float scale, int L)
{
    int idx  = blockIdx.x * blockDim.x + threadIdx.x;
    int pair = idx & 31;
    int row  = idx >> 5;
    int l    = row & (L - 1);
    float* p = t + (size_t)row * 64;
    float x1 = p[pair], x2 = p[pair + 32];
    float th1 = pos[l * 64 + pair];
    float th2 = pos[l * 64 + pair + 32];
    float s1, c1, s2, c2;
    sincosf(th1, &s1, &c1);
    sincosf(th2, &s2, &c2);
    p[pair]      = scale * (x1 * c1 - x2 * s1);
    p[pair + 32] = scale * (x2 * c2 + x1 * s2);
}

// ---------------------------------------------------------------------------
// Flash attention, FFMA2 inner loops.
// Block = (b,h) x 64 query rows. 256 threads, thread = 2 q-rows x 8 cols.
// Smem: Qs[64][65], KsT[64][66] (K transposed: [dim][row]), Vs[64][68],
//       Ps[64][65]. Packed pairs are contiguous in KsT rows / Vs rows.
// ---------------------------------------------------------------------------
#define QS_PAD 65
#define KT_PAD 66
#define VS_PAD 68
#define PS_PAD 65
#define OFF_QS 0
#define OFF_KT (64*QS_PAD)
#define OFF_VS (OFF_KT + 64*KT_PAD)
#define OFF_PS (OFF_VS + 64*VS_PAD)
#define SMEM_FLOATS (OFF_PS + 64*PS_PAD)

__global__ __launch_bounds__(256, 2)
void attn_kernel(const int* __restrict__ mask, float* __restrict__ X)
{
    extern __shared__ float sm[];
    float (*Qs)[QS_PAD]  = (float(*)[QS_PAD])(sm + OFF_QS);
    float (*KsT)[KT_PAD] = (float(*)[KT_PAD])(sm + OFF_KT);
    float (*Vs)[VS_PAD]  = (float(*)[VS_PAD])(sm + OFF_VS);
    float (*Ps)[PS_PAD]  = (float(*)[PS_PAD])(sm + OFF_PS);
    __shared__ int maskS[64];

    const int tid = threadIdx.x;
    const int bh  = blockIdx.x;
    const int b   = bh >> 4;
    const int h   = bh & 15;
    const int q0  = blockIdx.y * 64;
    const int i0  = (tid >> 3) * 2;
    const int i1  = i0 + 1;
    const int c0  = (tid & 7) * 8;

    const float* Qg = g_Q + ((size_t)bh * NQ + q0) * HD;
    for (int i4 = tid; i4 < 1024; i4 += 256) {
        float4 qv = ((const float4*)Qg)[i4];
        int r = i4 >> 4, c = (i4 & 15) * 4;
        Qs[r][c] = qv.x; Qs[r][c+1] = qv.y; Qs[r][c+2] = qv.z; Qs[r][c+3] = qv.w;
    }

    float m0v = -INFINITY, m1v = -INFINITY, l0v = 0.f, l1v = 0.f;
    u64 acc0[4], acc1[4];
    #pragma unroll
    for (int p = 0; p < 4; p++) { acc0[p] = 0ull; acc1[p] = 0ull; }

    for (int j0 = 0; j0 < NKV; j0 += 64) {
        __syncthreads();
        const float* Kg = g_K + ((size_t)bh * NKV + j0) * HD;
        const float* Vg = g_V + ((size_t)bh * NKV + j0) * HD;
        for (int i4 = tid; i4 < 1024; i4 += 256) {
            int r = i4 >> 4, c = (i4 & 15) * 4;
            float4 kv = ((const float4*)Kg)[i4];
            KsT[c+0][r] = kv.x; KsT[c+1][r] = kv.y;
            KsT[c+2][r] = kv.z; KsT[c+3][r] = kv.w;
            float4 vv = ((const float4*)Vg)[i4];
            *(float4*)(&Vs[r][c]) = vv;
        }
        if (tid < 64) maskS[tid] = mask[b * NKV + j0 + tid];
        __syncthreads();

        // S = Q @ K^T : packed over column pairs (contiguous in KsT rows)
        u64 sp0[4], sp1[4];
        #pragma unroll
        for (int p = 0; p < 4; p++) { sp0[p] = 0ull; sp1[p] = 0ull; }
        #pragma unroll 4
        for (int dd = 0; dd < 64; dd++) {
            u64 qa = dup2(Qs[i0][dd]);
            u64 qb = dup2(Qs[i1][dd]);
            const u64* kp = (const u64*)(&KsT[dd][c0]);
            #pragma unroll
            for (int p = 0; p < 4; p++) {
                u64 k2 = kp[p];
                ffma2(sp0[p], qa, k2);
                ffma2(sp1[p], qb, k2);
            }
        }
        float s0[8], s1[8];
        #pragma unroll
        for (int p = 0; p < 4; p++) {
            unpack2(sp0[p], s0[2*p], s0[2*p+1]);
            unpack2(sp1[p], s1[2*p], s1[2*p+1]);
        }

        // Mask + streaming softmax
        float mt0 = -FLT_MAX, mt1 = -FLT_MAX;
        #pragma unroll
        for (int jj = 0; jj < 8; jj++) {
            if (maskS[c0 + jj] == 0) { s0[jj] = -FLT_MAX; s1[jj] = -FLT_MAX; }
            mt0 = fmaxf(mt0, s0[jj]); mt1 = fmaxf(mt1, s1[jj]);
        }
        #pragma unroll
        for (int o = 4; o >= 1; o >>= 1) {
            mt0 = fmaxf(mt0, __shfl_xor_sync(0xffffffffu, mt0, o));
            mt1 = fmaxf(mt1, __shfl_xor_sync(0xffffffffu, mt1, o));
        }
        float nm0 = fmaxf(m0v, mt0), nm1 = fmaxf(m1v, mt1);
        float a0 = __expf(m0v - nm0), a1 = __expf(m1v - nm1);

        float ls0 = 0.f, ls1 = 0.f;
        #pragma unroll
        for (int jj = 0; jj < 8; jj++) {
            float p0 = __expf(s0[jj] - nm0);
            float p1 = __expf(s1[jj] - nm1);
            Ps[i0][c0 + jj] = p0; Ps[i1][c0 + jj] = p1;
            ls0 += p0; ls1 += p1;
        }
        #pragma unroll
        for (int o = 4; o >= 1; o >>= 1) {
            ls0 += __shfl_xor_sync(0xffffffffu, ls0, o);
            ls1 += __shfl_xor_sync(0xffffffffu, ls1, o);
        }
        l0v = l0v * a0 + ls0;
        l1v = l1v * a1 + ls1;
        m0v = nm0; m1v = nm1;
        u64 a0d = dup2(a0), a1d = dup2(a1);
        #pragma unroll
        for (int p = 0; p < 4; p++) { fmul2(acc0[p], acc0[p], a0d); fmul2(acc1[p], acc1[p], a1d); }
        __syncthreads();

        // O += P @ V : packed over head-dim pairs (contiguous in Vs rows)
        #pragma unroll 4
        for (int j = 0; j < 64; j++) {
            u64 pa = dup2(Ps[i0][j]);
            u64 pb = dup2(Ps[i1][j]);
            const u64* vp = (const u64*)(&Vs[j][c0]);
            #pragma unroll
            for (int p = 0; p < 4; p++) {
                u64 v2 = vp[p];
                ffma2(acc0[p], pa, v2);
                ffma2(acc1[p], pb, v2);
            }
        }
    }

    float inv0 = 1.f / l0v, inv1 = 1.f / l1v;
    float o0[8], o1[8];
    #pragma unroll
    for (int p = 0; p < 4; p++) {
        unpack2(acc0[p], o0[2*p], o0[2*p+1]);
        unpack2(acc1[p], o1[2*p], o1[2*p+1]);
    }
    float* x0 = X + ((size_t)(b * NQ + q0 + i0) * C_) + h * HD + c0;
    float* x1 = X + ((size_t)(b * NQ + q0 + i1) * C_) + h * HD + c0;
    #pragma unroll
    for (int d = 0; d < 8; d++) { x0[d] = o0[d] * inv0; x1[d] = o1[d] * inv1; }
}

// ---------------------------------------------------------------------------
extern "C" void kernel_launch(void* const* d_in, const int* in_sizes, int n_in,
                              void* d_out, int out_size)
{
    const float* q    = (const float*)d_in[0];
    const float* k    = (const float*)d_in[1];
    const float* v    = (const float*)d_in[2];
    const int*   mask = (const int*)  d_in[3];
    const float* pos  = (const float*)d_in[4];
    const float* qW   = (const float*)d_in[5];
    const float* kW   = (const float*)d_in[6];
    const float* vW   = (const float*)d_in[7];
    const float* pW   = (const float*)d_in[8];
    float* out = (float*)d_out;

    float *Qp, *Kp, *Vp, *Xp;
    cudaGetSymbolAddress((void**)&Qp, g_Q);
    cudaGetSymbolAddress((void**)&Kp, g_K);
    cudaGetSymbolAddress((void**)&Vp, g_V);
    cudaGetSymbolAddress((void**)&Xp, g_X);

    const int SMEM_ATT = SMEM_FLOATS * (int)sizeof(float);
    cudaFuncSetAttribute(attn_kernel, cudaFuncAttributeMaxDynamicSharedMemorySize, SMEM_ATT);

    dim3 gg(C_ / 128, M_ / 128, 3);
    gemm_proj<<<gg, 256>>>(q, k, v, qW, kW, vW, Qp, Kp, Vp);

    int ropeBlocks = (B_ * H_ * NQ * 32) / 256;
    rope_kernel<<<ropeBlocks, 256>>>(Qp, pos, 0.125f, NQ);
    rope_kernel<<<ropeBlocks, 256>>>(Kp, pos, 1.0f, NKV);

    attn_kernel<<<dim3(B_ * H_, NQ / 64), 256, SMEM_ATT>>>(mask, Xp);

    gemm_out<<<dim3(C_ / 128, M_ / 128), 256>>>(Xp, pW, out);
}

// round 3
// speedup vs baseline: 1.1016x; 1.0014x over previous
#include <cuda_runtime.h>
#include <float.h>
#include <math.h>

// Problem shape (fixed)
#define B_   2
#define NQ   2048
#define NKV  2048
#define C_   1024
#define H_   16
#define HD   64
#define M_   (B_*NQ)   // 4096

typedef unsigned long long u64;

// ---- packed f32x2 helpers (sm_103a FFMA2 path) ------------------------------
__device__ __forceinline__ u64 pack2(float lo, float hi) {
    u64 r; asm("mov.b64 %0, {%1,%2};" : "=l"(r) : "f"(lo), "f"(hi)); return r;
}
__device__ __forceinline__ u64 dup2(float x) { return pack2(x, x); }
__device__ __forceinline__ void unpack2(u64 v, float& lo, float& hi) {
    asm("mov.b64 {%0,%1}, %2;" : "=f"(lo), "=f"(hi) : "l"(v));
}
__device__ __forceinline__ void ffma2(u64& d, u64 a, u64 b) {
    asm("fma.rn.f32x2 %0, %1, %2, %3;" : "=l"(d) : "l"(a), "l"(b), "l"(d));
}
__device__ __forceinline__ void fmul2(u64& d, u64 a, u64 b) {
    asm("mul.rn.f32x2 %0, %1, %2;" : "=l"(d) : "l"(a), "l"(b));
}

// Scratch (allocation-free: device globals)
__device__ float g_Q[B_*H_*NQ*HD];
__device__ float g_K[B_*H_*NKV*HD];
__device__ float g_V[B_*H_*NKV*HD];
__device__ float g_X[B_*NQ*C_];

// ---------------------------------------------------------------------------
// Tiled SGEMM body: out[M,N] = A[M,K] @ W[K,N], FFMA2 inner loop.
// EPI=0: row-major write. EPI=1: head-split write to [B,H,L,hd].
// ---------------------------------------------------------------------------
template<int EPI>
__device__ __forceinline__
void gemm_body(const float* __restrict__ A, const float* __restrict__ W,
               float* __restrict__ out, int M, int N, int K, int L)
{
    __shared__ float As[16][128];   // As[k][m]
    __shared__ float Bs[16][128];   // Bs[k][n]

    const int tid = threadIdx.x;
    const int tx  = tid & 15;
    const int ty  = tid >> 4;
    const int m0  = blockIdx.y * 128;
    const int n0  = blockIdx.x * 128;

    u64 acc[8][4];
    #pragma unroll
    for (int i = 0; i < 8; i++)
        #pragma unroll
        for (int p = 0; p < 4; p++) acc[i][p] = 0ull;

    for (int k0 = 0; k0 < K; k0 += 16) {
        #pragma unroll
        for (int it = 0; it < 2; it++) {
            int idx = tid + it * 256;
            int row = idx >> 2, kq = idx & 3;
            float4 av = *(const float4*)(A + (size_t)(m0 + row) * K + k0 + kq * 4);
            As[kq*4+0][row] = av.x; As[kq*4+1][row] = av.y;
            As[kq*4+2][row] = av.z; As[kq*4+3][row] = av.w;
            int kr = idx >> 5, nq = idx & 31;
            *(float4*)(&Bs[kr][nq*4]) =
                *(const float4*)(W + (size_t)(k0 + kr) * N + n0 + nq * 4);
        }
        __syncthreads();

        #pragma unroll
        for (int kk = 0; kk < 16; kk++) {
            float ra[8];
            *(float4*)(ra)     = *(const float4*)(&As[kk][ty*8]);
            *(float4*)(ra + 4) = *(const float4*)(&As[kk][ty*8 + 4]);
            u64 rb[4];
            const u64* bp = (const u64*)(&Bs[kk][tx*8]);
            rb[0] = bp[0]; rb[1] = bp[1]; rb[2] = bp[2]; rb[3] = bp[3];
            #pragma unroll
            for (int i = 0; i < 8; i++) {
                u64 ad = dup2(ra[i]);
                #pragma unroll
                for (int p = 0; p < 4; p++) ffma2(acc[i][p], ad, rb[p]);
            }
        }
        __syncthreads();
    }

    #pragma unroll
    for (int i = 0; i < 8; i++) {
        int m = m0 + ty * 8 + i;
        float v[8];
        #pragma unroll
        for (int p = 0; p < 4; p++) unpack2(acc[i][p], v[2*p], v[2*p+1]);
        if (EPI == 0) {
            float* o = out + (size_t)m * N + n0 + tx * 8;
            *(float4*)(o)     = make_float4(v[0], v[1], v[2], v[3]);
            *(float4*)(o + 4) = make_float4(v[4], v[5], v[6], v[7]);
        } else {
            int b = m / L, l = m % L;
            #pragma unroll
            for (int j = 0; j < 8; j++) {
                int n = n0 + tx * 8 + j;
                int h = n >> 6, d = n & 63;
                out[(((size_t)(b * H_ + h) * L + l) << 6) + d] = v[j];
            }
        }
    }
}

// Fused q/k/v projection: blockIdx.z picks the GEMM (768 blocks total)
__global__ __launch_bounds__(256)
void gemm_proj(const float* __restrict__ q, const float* __restrict__ k,
               const float* __restrict__ v,
               const float* __restrict__ qW, const float* __restrict__ kW,
               const float* __restrict__ vW,
               float* __restrict__ Q, float* __restrict__ K, float* __restrict__ V)
{
    int z = blockIdx.z;
    const float* A = (z == 0) ? q  : (z == 1) ? k  : v;
    const float* W = (z == 0) ? qW : (z == 1) ? kW : vW;
    float* O       = (z == 0) ? Q  : (z == 1) ? K  : V;
    gemm_body<1>(A, W, O, M_, C_, C_, NQ);
}

__global__ __launch_bounds__(256)
void gemm_out(const float* __restrict__ A, const float* __restrict__ W,
              float* __restrict__ out)
{
    gemm_body<0>(A, W, out, M_, C_, C_, NQ);
}

// ---------------------------------------------------------------------------
// In-place RoPE on [B,H,L,hd]
// ---------------------------------------------------------------------------
__global__ __launch_bounds__(256)
void rope_kernel(float* __restrict__ t, const float* __restrict__ pos,
                 float scale, int L)
{
    int idx  = blockIdx.x * blockDim.x + threadIdx.x;
    int pair = idx & 31;
    int row  = idx >> 5;
    int l    = row & (L - 1);
    float* p = t + (size_t)row * 64;
    float x1 = p[pair], x2 = p[pair + 32];
    float th1 = pos[l * 64 + pair];
    float th2 = pos[l * 64 + pair + 32];
    float s1, c1, s2, c2;
    sincosf(th1, &s1, &c1);
    sincosf(th2, &s2, &c2);
    p[pair]      = scale * (x1 * c1 - x2 * s1);
    p[pair + 32] = scale * (x2 * c2 + x1 * s2);
}

// ---------------------------------------------------------------------------
// Flash attention, FFMA2 inner loops.
// Block = (b,h) x 64 query rows. 256 threads, thread = 2 q-rows x 8 cols.
// Smem: Qs[64][65], KsT[64][66] (K transposed: [dim][row]), Vs[64][68],
//       Ps[64][65]. Packed pairs are contiguous in KsT rows / Vs rows.
// ---------------------------------------------------------------------------
#define QS_PAD 65
#define KT_PAD 66
#define VS_PAD 68
#define PS_PAD 65
#define OFF_QS 0
#define OFF_KT (64*QS_PAD)
#define OFF_VS (OFF_KT + 64*KT_PAD)
#define OFF_PS (OFF_VS + 64*VS_PAD)
#define SMEM_FLOATS (OFF_PS + 64*PS_PAD)

__global__ __launch_bounds__(256, 2)
void attn_kernel(const int* __restrict__ mask, float* __restrict__ X)
{
    extern __shared__ float sm[];
    float (*Qs)[QS_PAD]  = (float(*)[QS_PAD])(sm + OFF_QS);
    float (*KsT)[KT_PAD] = (float(*)[KT_PAD])(sm + OFF_KT);
    float (*Vs)[VS_PAD]  = (float(*)[VS_PAD])(sm + OFF_VS);
    float (*Ps)[PS_PAD]  = (float(*)[PS_PAD])(sm + OFF_PS);
    __shared__ int maskS[64];

    const int tid = threadIdx.x;
    const int bh  = blockIdx.x;
    const int b   = bh >> 4;
    const int h   = bh & 15;
    const int q0  = blockIdx.y * 64;
    const int i0  = (tid >> 3) * 2;
    const int i1  = i0 + 1;
    const int c0  = (tid & 7) * 8;

    const float* Qg = g_Q + ((size_t)bh * NQ + q0) * HD;
    for (int i4 = tid; i4 < 1024; i4 += 256) {
        float4 qv = ((const float4*)Qg)[i4];
        int r = i4 >> 4, c = (i4 & 15) * 4;
        Qs[r][c] = qv.x; Qs[r][c+1] = qv.y; Qs[r][c+2] = qv.z; Qs[r][c+3] = qv.w;
    }

    float m0v = -INFINITY, m1v = -INFINITY, l0v = 0.f, l1v = 0.f;
    u64 acc0[4], acc1[4];
    #pragma unroll
    for (int p = 0; p < 4; p++) { acc0[p] = 0ull; acc1[p] = 0ull; }

    for (int j0 = 0; j0 < NKV; j0 += 64) {
        __syncthreads();
        const float* Kg = g_K + ((size_t)bh * NKV + j0) * HD;
        const float* Vg = g_V + ((size_t)bh * NKV + j0) * HD;
        for (int i4 = tid; i4 < 1024; i4 += 256) {
            int r = i4 >> 4, c = (i4 & 15) * 4;
            float4 kv = ((const float4*)Kg)[i4];
            KsT[c+0][r] = kv.x; KsT[c+1][r] = kv.y;
            KsT[c+2][r] = kv.z; KsT[c+3][r] = kv.w;
            float4 vv = ((const float4*)Vg)[i4];
            *(float4*)(&Vs[r][c]) = vv;
        }
        if (tid < 64) maskS[tid] = mask[b * NKV + j0 + tid];
        __syncthreads();

        // S = Q @ K^T : packed over column pairs (contiguous in KsT rows)
        u64 sp0[4], sp1[4];
        #pragma unroll
        for (int p = 0; p < 4; p++) { sp0[p] = 0ull; sp1[p] = 0ull; }
        #pragma unroll 4
        for (int dd = 0; dd < 64; dd++) {
            u64 qa = dup2(Qs[i0][dd]);
            u64 qb = dup2(Qs[i1][dd]);
            const u64* kp = (const u64*)(&KsT[dd][c0]);
            #pragma unroll
            for (int p = 0; p < 4; p++) {
                u64 k2 = kp[p];
                ffma2(sp0[p], qa, k2);
                ffma2(sp1[p], qb, k2);
            }
        }
        float s0[8], s1[8];
        #pragma unroll
        for (int p = 0; p < 4; p++) {
            unpack2(sp0[p], s0[2*p], s0[2*p+1]);
            unpack2(sp1[p], s1[2*p], s1[2*p+1]);
        }

        // Mask + streaming softmax
        float mt0 = -FLT_MAX, mt1 = -FLT_MAX;
        #pragma unroll
        for (int jj = 0; jj < 8; jj++) {
            if (maskS[c0 + jj] == 0) { s0[jj] = -FLT_MAX; s1[jj] = -FLT_MAX; }
            mt0 = fmaxf(mt0, s0[jj]); mt1 = fmaxf(mt1, s1[jj]);
        }
        #pragma unroll
        for (int o = 4; o >= 1; o >>= 1) {
            mt0 = fmaxf(mt0, __shfl_xor_sync(0xffffffffu, mt0, o));
            mt1 = fmaxf(mt1, __shfl_xor_sync(0xffffffffu, mt1, o));
        }
        float nm0 = fmaxf(m0v, mt0), nm1 = fmaxf(m1v, mt1);
        float a0 = __expf(m0v - nm0), a1 = __expf(m1v - nm1);

        float ls0 = 0.f, ls1 = 0.f;
        #pragma unroll
        for (int jj = 0; jj < 8; jj++) {
            float p0 = __expf(s0[jj] - nm0);
            float p1 = __expf(s1[jj] - nm1);
            Ps[i0][c0 + jj] = p0; Ps[i1][c0 + jj] = p1;
            ls0 += p0; ls1 += p1;
        }
        #pragma unroll
        for (int o = 4; o >= 1; o >>= 1) {
            ls0 += __shfl_xor_sync(0xffffffffu, ls0, o);
            ls1 += __shfl_xor_sync(0xffffffffu, ls1, o);
        }
        l0v = l0v * a0 + ls0;
        l1v = l1v * a1 + ls1;
        m0v = nm0; m1v = nm1;
        u64 a0d = dup2(a0), a1d = dup2(a1);
        #pragma unroll
        for (int p = 0; p < 4; p++) { fmul2(acc0[p], acc0[p], a0d); fmul2(acc1[p], acc1[p], a1d); }
        __syncthreads();

        // O += P @ V : packed over head-dim pairs (contiguous in Vs rows)
        #pragma unroll 4
        for (int j = 0; j < 64; j++) {
            u64 pa = dup2(Ps[i0][j]);
            u64 pb = dup2(Ps[i1][j]);
            const u64* vp = (const u64*)(&Vs[j][c0]);
            #pragma unroll
            for (int p = 0; p < 4; p++) {
                u64 v2 = vp[p];
                ffma2(acc0[p], pa, v2);
                ffma2(acc1[p], pb, v2);
            }
        }
    }

    float inv0 = 1.f / l0v, inv1 = 1.f / l1v;
    float o0[8], o1[8];
    #pragma unroll
    for (int p = 0; p < 4; p++) {
        unpack2(acc0[p], o0[2*p], o0[2*p+1]);
        unpack2(acc1[p], o1[2*p], o1[2*p+1]);
    }
    float* x0 = X + ((size_t)(b * NQ + q0 + i0) * C_) + h * HD + c0;
    float* x1 = X + ((size_t)(b * NQ + q0 + i1) * C_) + h * HD + c0;
    #pragma unroll
    for (int d = 0; d < 8; d++) { x0[d] = o0[d] * inv0; x1[d] = o1[d] * inv1; }
}

// ---------------------------------------------------------------------------
extern "C" void kernel_launch(void* const* d_in, const int* in_sizes, int n_in,
                              void* d_out, int out_size)
{
    const float* q    = (const float*)d_in[0];
    const float* k    = (const float*)d_in[1];
    const float* v    = (const float*)d_in[2];
    const int*   mask = (const int*)  d_in[3];
    const float* pos  = (const float*)d_in[4];
    const float* qW   = (const float*)d_in[5];
    const float* kW   = (const float*)d_in[6];
    const float* vW   = (const float*)d_in[7];
    const float* pW   = (const float*)d_in[8];
    float* out = (float*)d_out;

    float *Qp, *Kp, *Vp, *Xp;
    cudaGetSymbolAddress((void**)&Qp, g_Q);
    cudaGetSymbolAddress((void**)&Kp, g_K);
    cudaGetSymbolAddress((void**)&Vp, g_V);
    cudaGetSymbolAddress((void**)&Xp, g_X);

    const int SMEM_ATT = SMEM_FLOATS * (int)sizeof(float);
    cudaFuncSetAttribute(attn_kernel, cudaFuncAttributeMaxDynamicSharedMemorySize, SMEM_ATT);

    dim3 gg(C_ / 128, M_ / 128, 3);
    gemm_proj<<<gg, 256>>>(q, k, v, qW, kW, vW, Qp, Kp, Vp);

    int ropeBlocks = (B_ * H_ * NQ * 32) / 256;
    rope_kernel<<<ropeBlocks, 256>>>(Qp, pos, 0.125f, NQ);
    rope_kernel<<<ropeBlocks, 256>>>(Kp, pos, 1.0f, NKV);

    attn_kernel<<<dim3(B_ * H_, NQ / 64), 256, SMEM_ATT>>>(mask, Xp);

    gemm_out<<<dim3(C_ / 128, M_ / 128), 256>>>(Xp, pW, out);
}

// round 5
// speedup vs baseline: 2.5499x; 2.3147x over previous
#include <cuda_runtime.h>
#include <cuda_bf16.h>
#include <float.h>
#include <math.h>
#include <stdint.h>

#define B_   2
#define NQ   2048
#define NKV  2048
#define C_   1024
#define H_   16
#define HD   64
#define M_   (B_*NQ)

typedef unsigned long long u64;
typedef unsigned int u32;

// ---- packed f32x2 (FFMA2) helpers ----
__device__ __forceinline__ u64 pack2(float lo, float hi) {
    u64 r; asm("mov.b64 %0, {%1,%2};" : "=l"(r) : "f"(lo), "f"(hi)); return r;
}
__device__ __forceinline__ u64 dup2(float x) { return pack2(x, x); }
__device__ __forceinline__ void unpack2(u64 v, float& lo, float& hi) {
    asm("mov.b64 {%0,%1}, %2;" : "=f"(lo), "=f"(hi) : "l"(v));
}
__device__ __forceinline__ void ffma2(u64& d, u64 a, u64 b) {
    asm("fma.rn.f32x2 %0, %1, %2, %3;" : "=l"(d) : "l"(a), "l"(b), "l"(d));
}

// ---- mma.sync / ldmatrix helpers (portable tensor-core path) ----
__device__ __forceinline__ u32 smem_u32(const void* p) {
    u32 a;
    asm("{ .reg .u64 t; cvta.to.shared.u64 t, %1; cvt.u32.u64 %0, t; }" : "=r"(a) : "l"(p));
    return a;
}
__device__ __forceinline__ void mma_bf16(float* c, const u32* a, u32 b0, u32 b1) {
    asm volatile("mma.sync.aligned.m16n8k16.row.col.f32.bf16.bf16.f32 "
        "{%0,%1,%2,%3}, {%4,%5,%6,%7}, {%8,%9}, {%0,%1,%2,%3};"
        : "+f"(c[0]), "+f"(c[1]), "+f"(c[2]), "+f"(c[3])
        : "r"(a[0]), "r"(a[1]), "r"(a[2]), "r"(a[3]), "r"(b0), "r"(b1));
}
__device__ __forceinline__ void ldsm_x4(u32* r, u32 addr) {
    asm volatile("ldmatrix.sync.aligned.m8n8.x4.shared.b16 {%0,%1,%2,%3}, [%4];"
        : "=r"(r[0]), "=r"(r[1]), "=r"(r[2]), "=r"(r[3]) : "r"(addr));
}
__device__ __forceinline__ void ldsm_x2(u32& r0, u32& r1, u32 addr) {
    asm volatile("ldmatrix.sync.aligned.m8n8.x2.shared.b16 {%0,%1}, [%2];"
        : "=r"(r0), "=r"(r1) : "r"(addr));
}
__device__ __forceinline__ void ldsm_x2t(u32& r0, u32& r1, u32 addr) {
    asm volatile("ldmatrix.sync.aligned.m8n8.x2.trans.shared.b16 {%0,%1}, [%2];"
        : "=r"(r0), "=r"(r1) : "r"(addr));
}

__device__ __forceinline__ void bsplit(float x, __nv_bfloat16& h, __nv_bfloat16& l) {
    h = __float2bfloat16(x);
    l = __float2bfloat16(x - __bfloat162float(h));
}
__device__ __forceinline__ u32 pack_bf(__nv_bfloat16 a, __nv_bfloat16 b) {
    return (u32)__bfloat16_as_ushort(a) | ((u32)__bfloat16_as_ushort(b) << 16);
}

// ---- scratch ----
__device__ float g_Q[B_*H_*NQ*HD];
__device__ float g_K[B_*H_*NKV*HD];
__device__ float g_V[B_*H_*NKV*HD];
__device__ float g_X[B_*NQ*C_];
__device__ __nv_bfloat16 g_Qh[B_*H_*NQ*HD],  g_Ql[B_*H_*NQ*HD];
__device__ __nv_bfloat16 g_Kh[B_*H_*NKV*HD], g_Kl[B_*H_*NKV*HD];
__device__ __nv_bfloat16 g_Vh[B_*H_*NKV*HD], g_Vl[B_*H_*NKV*HD];

// ============================================================================
// FFMA2 tiled SGEMM (proven R2)
// ============================================================================
template<int EPI>
__device__ __forceinline__
void gemm_body(const float* __restrict__ A, const float* __restrict__ W,
               float* __restrict__ out, int M, int N, int K, int L)
{
    __shared__ float As[16][128];
    __shared__ float Bs[16][128];
    const int tid = threadIdx.x, tx = tid & 15, ty = tid >> 4;
    const int m0 = blockIdx.y * 128, n0 = blockIdx.x * 128;

    u64 acc[8][4];
    #pragma unroll
    for (int i = 0; i < 8; i++)
        #pragma unroll
        for (int p = 0; p < 4; p++) acc[i][p] = 0ull;

    for (int k0 = 0; k0 < K; k0 += 16) {
        #pragma unroll
        for (int it = 0; it < 2; it++) {
            int idx = tid + it * 256;
            int row = idx >> 2, kq = idx & 3;
            float4 av = *(const float4*)(A + (size_t)(m0 + row) * K + k0 + kq * 4);
            As[kq*4+0][row] = av.x; As[kq*4+1][row] = av.y;
            As[kq*4+2][row] = av.z; As[kq*4+3][row] = av.w;
            int kr = idx >> 5, nq = idx & 31;
            *(float4*)(&Bs[kr][nq*4]) = *(const float4*)(W + (size_t)(k0 + kr) * N + n0 + nq * 4);
        }
        __syncthreads();
        #pragma unroll
        for (int kk = 0; kk < 16; kk++) {
            float ra[8];
            *(float4*)(ra)     = *(const float4*)(&As[kk][ty*8]);
            *(float4*)(ra + 4) = *(const float4*)(&As[kk][ty*8 + 4]);
            u64 rb[4];
            const u64* bp = (const u64*)(&Bs[kk][tx*8]);
            rb[0] = bp[0]; rb[1] = bp[1]; rb[2] = bp[2]; rb[3] = bp[3];
            #pragma unroll
            for (int i = 0; i < 8; i++) {
                u64 ad = dup2(ra[i]);
                #pragma unroll
                for (int p = 0; p < 4; p++) ffma2(acc[i][p], ad, rb[p]);
            }
        }
        __syncthreads();
    }
    #pragma unroll
    for (int i = 0; i < 8; i++) {
        int m = m0 + ty * 8 + i;
        float v[8];
        #pragma unroll
        for (int p = 0; p < 4; p++) unpack2(acc[i][p], v[2*p], v[2*p+1]);
        if (EPI == 0) {
            float* o = out + (size_t)m * N + n0 + tx * 8;
            *(float4*)(o)     = make_float4(v[0], v[1], v[2], v[3]);
            *(float4*)(o + 4) = make_float4(v[4], v[5], v[6], v[7]);
        } else {
            int b = m / L, l = m % L;
            #pragma unroll
            for (int j = 0; j < 8; j++) {
                int n = n0 + tx * 8 + j;
                out[(((size_t)(b * H_ + (n >> 6)) * L + l) << 6) + (n & 63)] = v[j];
            }
        }
    }
}

__global__ __launch_bounds__(256)
void gemm_proj(const float* __restrict__ q, const float* __restrict__ k,
               const float* __restrict__ v, const float* __restrict__ qW,
               const float* __restrict__ kW, const float* __restrict__ vW,
               float* __restrict__ Q, float* __restrict__ K, float* __restrict__ V)
{
    int z = blockIdx.z;
    const float* A = (z == 0) ? q  : (z == 1) ? k  : v;
    const float* W = (z == 0) ? qW : (z == 1) ? kW : vW;
    float* O       = (z == 0) ? Q  : (z == 1) ? K  : V;
    gemm_body<1>(A, W, O, M_, C_, C_, NQ);
}
__global__ __launch_bounds__(256)
void gemm_out(const float* __restrict__ A, const float* __restrict__ W, float* __restrict__ out)
{
    gemm_body<0>(A, W, out, M_, C_, C_, NQ);
}

// ============================================================================
// RoPE + bf16 hi/lo split
// ============================================================================
__global__ __launch_bounds__(256)
void rope_convert(const float* __restrict__ t, __nv_bfloat16* __restrict__ oh,
                  __nv_bfloat16* __restrict__ ol, const float* __restrict__ pos,
                  float scale, int L)
{
    int idx = blockIdx.x * blockDim.x + threadIdx.x;
    int pair = idx & 31, row = idx >> 5, l = row & (L - 1);
    const float* p = t + (size_t)row * 64;
    float x1 = p[pair], x2 = p[pair + 32];
    float s1, c1, s2, c2;
    sincosf(pos[l * 64 + pair], &s1, &c1);
    sincosf(pos[l * 64 + pair + 32], &s2, &c2);
    float y1 = scale * (x1 * c1 - x2 * s1);
    float y2 = scale * (x2 * c2 + x1 * s2);
    __nv_bfloat16 h, lo;
    bsplit(y1, h, lo);
    oh[(size_t)row*64 + pair] = h;  ol[(size_t)row*64 + pair] = lo;
    bsplit(y2, h, lo);
    oh[(size_t)row*64 + pair + 32] = h;  ol[(size_t)row*64 + pair + 32] = lo;
}

// ============================================================================
// V hi/lo split (same layout, no transpose needed for ldmatrix.trans path)
// ============================================================================
__global__ __launch_bounds__(256)
void v_split(const float* __restrict__ v, __nv_bfloat16* __restrict__ oh,
             __nv_bfloat16* __restrict__ ol)
{
    int i = blockIdx.x * blockDim.x + threadIdx.x;   // one float4 each
    float4 x = ((const float4*)v)[i];
    __nv_bfloat16 h0,l0,h1,l1,h2,l2,h3,l3;
    bsplit(x.x, h0, l0); bsplit(x.y, h1, l1);
    bsplit(x.z, h2, l2); bsplit(x.w, h3, l3);
    ((u32*)oh)[2*i]   = pack_bf(h0, h1);
    ((u32*)oh)[2*i+1] = pack_bf(h2, h3);
    ((u32*)ol)[2*i]   = pack_bf(l0, l1);
    ((u32*)ol)[2*i+1] = pack_bf(l2, l3);
}

// ============================================================================
// Flash attention with mma.sync bf16 (split hi/lo, 3 combos).
// CTA: 64 q-rows x one (b,h), 4 warps (warp = 16 q-rows). KV tiles of 64.
// ============================================================================
#define ROWP 72   // smem row pad (bf16 elems): 144B rows -> conflict-free ldmatrix

__global__ __launch_bounds__(128)
void attn_mma(const int* __restrict__ mask,
              const __nv_bfloat16* __restrict__ Qh, const __nv_bfloat16* __restrict__ Ql,
              const __nv_bfloat16* __restrict__ Kh, const __nv_bfloat16* __restrict__ Kl,
              const __nv_bfloat16* __restrict__ Vh, const __nv_bfloat16* __restrict__ Vl,
              float* __restrict__ X)
{
    __shared__ __nv_bfloat16 sKh[64][ROWP], sKl[64][ROWP];
    __shared__ __nv_bfloat16 sVh[64][ROWP], sVl[64][ROWP];
    __shared__ int s_mask[64];

    const int tid  = threadIdx.x;
    const int wid  = tid >> 5, lane = tid & 31;
    const int g    = lane >> 2, tig = lane & 3;
    const int bh   = blockIdx.x, b = bh >> 4, h = bh & 15;
    const int q0   = blockIdx.y * 64;
    const int r0   = wid * 16;             // warp's first q-row in tile

    const u32 baseKh = smem_u32(&sKh[0][0]);
    const u32 baseKl = smem_u32(&sKl[0][0]);
    const u32 baseVh = smem_u32(&sVh[0][0]);
    const u32 baseVl = smem_u32(&sVl[0][0]);

    // ---- stage Q (reuse K buffers), build Q fragments, then free ----
    {
        const __nv_bfloat16* qh = Qh + ((size_t)bh * NQ + q0) * HD;
        const __nv_bfloat16* ql = Ql + ((size_t)bh * NQ + q0) * HD;
        for (int i = tid; i < 512; i += 128) {
            int row = i >> 3, c8 = i & 7;
            *(float4*)(&sKh[row][c8*8]) = *(const float4*)(qh + row*64 + c8*8);
            *(float4*)(&sKl[row][c8*8]) = *(const float4*)(ql + row*64 + c8*8);
        }
    }
    __syncthreads();

    u32 qh[4][4], ql[4][4];
    {
        // x4 addresses: lanes 0-15 -> rows 0..15 @ col k0; lanes 16-31 -> rows @ col k0+8
        u32 rowoff = (u32)((r0 + (lane & 15)) * ROWP + ((lane >> 4) << 3)) * 2;
        #pragma unroll
        for (int kk = 0; kk < 4; kk++) {
            ldsm_x4(qh[kk], baseKh + rowoff + kk * 32);
            ldsm_x4(ql[kk], baseKl + rowoff + kk * 32);
        }
    }

    float oacc[8][4];
    #pragma unroll
    for (int nn = 0; nn < 8; nn++)
        #pragma unroll
        for (int p = 0; p < 4; p++) oacc[nn][p] = 0.f;
    float lacc0 = 0.f, lacc1 = 0.f;

    // per-lane ldmatrix address components
    const u32 kAddrLane = (u32)((lane & 7) * ROWP + ((lane >> 3) & 1) * 8) * 2;  // + (8nn*ROWP + 16kk)*2
    const u32 vAddrLane = (u32)((lane & 15) * ROWP) * 2;                          // + (16kk*ROWP + 8nn)*2

    for (int t = 0; t < NKV / 64; t++) {
        __syncthreads();   // previous tile fully consumed (also protects Q staging)
        {
            const __nv_bfloat16* kh = Kh + ((size_t)bh * NKV + t*64) * HD;
            const __nv_bfloat16* kl = Kl + ((size_t)bh * NKV + t*64) * HD;
            const __nv_bfloat16* vh = Vh + ((size_t)bh * NKV + t*64) * HD;
            const __nv_bfloat16* vl = Vl + ((size_t)bh * NKV + t*64) * HD;
            for (int i = tid; i < 512; i += 128) {
                int row = i >> 3, c8 = i & 7;
                *(float4*)(&sKh[row][c8*8]) = *(const float4*)(kh + row*64 + c8*8);
                *(float4*)(&sKl[row][c8*8]) = *(const float4*)(kl + row*64 + c8*8);
                *(float4*)(&sVh[row][c8*8]) = *(const float4*)(vh + row*64 + c8*8);
                *(float4*)(&sVl[row][c8*8]) = *(const float4*)(vl + row*64 + c8*8);
            }
            if (tid < 64) s_mask[tid] = mask[b * NKV + t*64 + tid];
        }
        __syncthreads();

        // ---- S = Q @ K^T (16 x 64 per warp), 3 split combos ----
        float sacc[8][4];
        #pragma unroll
        for (int nn = 0; nn < 8; nn++)
            #pragma unroll
            for (int p = 0; p < 4; p++) sacc[nn][p] = 0.f;

        #pragma unroll
        for (int kk = 0; kk < 4; kk++) {
            #pragma unroll
            for (int nn = 0; nn < 8; nn++) {
                u32 off = kAddrLane + (u32)(nn * 8 * ROWP + kk * 16) * 2;
                u32 bh0, bh1, bl0, bl1;
                ldsm_x2(bh0, bh1, baseKh + off);
                ldsm_x2(bl0, bl1, baseKl + off);
                mma_bf16(sacc[nn], qh[kk], bh0, bh1);
                mma_bf16(sacc[nn], qh[kk], bl0, bl1);
                mma_bf16(sacc[nn], ql[kk], bh0, bh1);
            }
        }

        // ---- mask + exp + pack P fragments (C-frag layout == A-frag layout) ----
        u32 ph[4][4], pl[4][4];
        #pragma unroll
        for (int nn = 0; nn < 8; nn++) {
            int m0 = s_mask[nn*8 + 2*tig], m1 = s_mask[nn*8 + 2*tig + 1];
            float p00 = m0 ? __expf(sacc[nn][0]) : 0.f;
            float p01 = m1 ? __expf(sacc[nn][1]) : 0.f;
            float p10 = m0 ? __expf(sacc[nn][2]) : 0.f;
            float p11 = m1 ? __expf(sacc[nn][3]) : 0.f;
            lacc0 += p00 + p01;
            lacc1 += p10 + p11;
            __nv_bfloat16 a, bb;
            int kk = nn >> 1, hi = nn & 1;
            bsplit(p00, a, bb); __nv_bfloat16 c, d; bsplit(p01, c, d);
            ph[kk][hi ? 2 : 0] = pack_bf(a, c);
            pl[kk][hi ? 2 : 0] = pack_bf(bb, d);
            bsplit(p10, a, bb); bsplit(p11, c, d);
            ph[kk][hi ? 3 : 1] = pack_bf(a, c);
            pl[kk][hi ? 3 : 1] = pack_bf(bb, d);
        }

        // ---- O += P @ V (16 x 64 per warp), 3 split combos ----
        #pragma unroll
        for (int kk = 0; kk < 4; kk++) {
            #pragma unroll
            for (int nn = 0; nn < 8; nn++) {
                u32 off = vAddrLane + (u32)(kk * 16 * ROWP + nn * 8) * 2;
                u32 bh0, bh1, bl0, bl1;
                ldsm_x2t(bh0, bh1, baseVh + off);
                ldsm_x2t(bl0, bl1, baseVl + off);
                mma_bf16(oacc[nn], ph[kk], bh0, bh1);
                mma_bf16(oacc[nn], ph[kk], bl0, bl1);
                mma_bf16(oacc[nn], pl[kk], bh0, bh1);
            }
        }
    }

    // ---- row-sum reduce over the 4 lanes sharing a row, write output ----
    lacc0 += __shfl_xor_sync(0xffffffffu, lacc0, 1);
    lacc0 += __shfl_xor_sync(0xffffffffu, lacc0, 2);
    lacc1 += __shfl_xor_sync(0xffffffffu, lacc1, 1);
    lacc1 += __shfl_xor_sync(0xffffffffu, lacc1, 2);
    float inv0 = 1.f / lacc0, inv1 = 1.f / lacc1;

    int row0 = q0 + r0 + g, row1 = row0 + 8;
    float* x0 = X + (size_t)(b * NQ + row0) * C_ + h * 64;
    float* x1 = X + (size_t)(b * NQ + row1) * C_ + h * 64;
    #pragma unroll
    for (int nn = 0; nn < 8; nn++) {
        int c = nn * 8 + 2 * tig;
        *(float2*)(x0 + c) = make_float2(oacc[nn][0] * inv0, oacc[nn][1] * inv0);
        *(float2*)(x1 + c) = make_float2(oacc[nn][2] * inv1, oacc[nn][3] * inv1);
    }
}

// ============================================================================
extern "C" void kernel_launch(void* const* d_in, const int* in_sizes, int n_in,
                              void* d_out, int out_size)
{
    const float* q    = (const float*)d_in[0];
    const float* k    = (const float*)d_in[1];
    const float* v    = (const float*)d_in[2];
    const int*   mask = (const int*)  d_in[3];
    const float* pos  = (const float*)d_in[4];
    const float* qW   = (const float*)d_in[5];
    const float* kW   = (const float*)d_in[6];
    const float* vW   = (const float*)d_in[7];
    const float* pW   = (const float*)d_in[8];
    float* out = (float*)d_out;

    float *Qp, *Kp, *Vp, *Xp;
    cudaGetSymbolAddress((void**)&Qp, g_Q);
    cudaGetSymbolAddress((void**)&Kp, g_K);
    cudaGetSymbolAddress((void**)&Vp, g_V);
    cudaGetSymbolAddress((void**)&Xp, g_X);
    __nv_bfloat16 *Qh, *Ql, *Kh, *Kl, *Vh, *Vl;
    cudaGetSymbolAddress((void**)&Qh, g_Qh);
    cudaGetSymbolAddress((void**)&Ql, g_Ql);
    cudaGetSymbolAddress((void**)&Kh, g_Kh);
    cudaGetSymbolAddress((void**)&Kl, g_Kl);
    cudaGetSymbolAddress((void**)&Vh, g_Vh);
    cudaGetSymbolAddress((void**)&Vl, g_Vl);

    dim3 gg(C_ / 128, M_ / 128, 3);
    gemm_proj<<<gg, 256>>>(q, k, v, qW, kW, vW, Qp, Kp, Vp);

    int rb = (B_ * H_ * NQ * 32) / 256;
    rope_convert<<<rb, 256>>>(Qp, Qh, Ql, pos, 0.125f, NQ);
    rope_convert<<<rb, 256>>>(Kp, Kh, Kl, pos, 1.0f, NKV);
    v_split<<<(B_*H_*NKV*HD/4) / 256, 256>>>(Vp, Vh, Vl);

    attn_mma<<<dim3(B_ * H_, NQ / 64), 128>>>(mask, Qh, Ql, Kh, Kl, Vh, Vl, Xp);

    gemm_out<<<dim3(C_ / 128, M_ / 128), 256>>>(Xp, pW, out);
}

// round 6
// speedup vs baseline: 4.3409x; 1.7024x over previous
#include <cuda_runtime.h>
#include <cuda_bf16.h>
#include <float.h>
#include <math.h>
#include <stdint.h>

#define B_   2
#define NQ   2048
#define NKV  2048
#define C_   1024
#define H_   16
#define HD   64
#define M_   (B_*NQ)

typedef unsigned long long u64;
typedef unsigned int u32;

// ---- mma.sync / ldmatrix helpers ----
__device__ __forceinline__ u32 smem_u32(const void* p) {
    u32 a;
    asm("{ .reg .u64 t; cvta.to.shared.u64 t, %1; cvt.u32.u64 %0, t; }" : "=r"(a) : "l"(p));
    return a;
}
__device__ __forceinline__ void mma_bf16(float* c, const u32* a, u32 b0, u32 b1) {
    asm volatile("mma.sync.aligned.m16n8k16.row.col.f32.bf16.bf16.f32 "
        "{%0,%1,%2,%3}, {%4,%5,%6,%7}, {%8,%9}, {%0,%1,%2,%3};"
        : "+f"(c[0]), "+f"(c[1]), "+f"(c[2]), "+f"(c[3])
        : "r"(a[0]), "r"(a[1]), "r"(a[2]), "r"(a[3]), "r"(b0), "r"(b1));
}
__device__ __forceinline__ void ldsm_x4(u32* r, u32 addr) {
    asm volatile("ldmatrix.sync.aligned.m8n8.x4.shared.b16 {%0,%1,%2,%3}, [%4];"
        : "=r"(r[0]), "=r"(r[1]), "=r"(r[2]), "=r"(r[3]) : "r"(addr));
}
__device__ __forceinline__ void ldsm_x2(u32& r0, u32& r1, u32 addr) {
    asm volatile("ldmatrix.sync.aligned.m8n8.x2.shared.b16 {%0,%1}, [%2];"
        : "=r"(r0), "=r"(r1) : "r"(addr));
}
__device__ __forceinline__ void ldsm_x2t(u32& r0, u32& r1, u32 addr) {
    asm volatile("ldmatrix.sync.aligned.m8n8.x2.trans.shared.b16 {%0,%1}, [%2];"
        : "=r"(r0), "=r"(r1) : "r"(addr));
}
__device__ __forceinline__ void cpa16(u32 dst, const void* src) {
    asm volatile("cp.async.cg.shared.global [%0], [%1], 16;" :: "r"(dst), "l"(src));
}
#define CPA_COMMIT() asm volatile("cp.async.commit_group;" ::: "memory")
#define CPA_WAIT1()  asm volatile("cp.async.wait_group 1;" ::: "memory")

__device__ __forceinline__ void bsplit(float x, __nv_bfloat16& h, __nv_bfloat16& l) {
    h = __float2bfloat16(x);
    l = __float2bfloat16(x - __bfloat162float(h));
}
__device__ __forceinline__ u32 pack_bf(__nv_bfloat16 a, __nv_bfloat16 b) {
    return (u32)__bfloat16_as_ushort(a) | ((u32)__bfloat16_as_ushort(b) << 16);
}

// ---- scratch ----
__device__ float g_Q[B_*H_*NQ*HD];
__device__ float g_K[B_*H_*NKV*HD];
__device__ float g_V[B_*H_*NKV*HD];
__device__ float g_X[B_*NQ*C_];
__device__ __nv_bfloat16 g_Qh[B_*H_*NQ*HD],  g_Ql[B_*H_*NQ*HD];
__device__ __nv_bfloat16 g_Kh[B_*H_*NKV*HD], g_Kl[B_*H_*NKV*HD];
__device__ __nv_bfloat16 g_Vh[B_*H_*NKV*HD], g_Vl[B_*H_*NKV*HD];
// GEMM operands (hi/lo splits)
__device__ __nv_bfloat16 g_Iqh[M_*C_], g_Iql[M_*C_];
__device__ __nv_bfloat16 g_Ikh[M_*C_], g_Ikl[M_*C_];
__device__ __nv_bfloat16 g_Ivh[M_*C_], g_Ivl[M_*C_];
__device__ __nv_bfloat16 g_Wqh[C_*C_], g_Wql[C_*C_];
__device__ __nv_bfloat16 g_Wkh[C_*C_], g_Wkl[C_*C_];
__device__ __nv_bfloat16 g_Wvh[C_*C_], g_Wvl[C_*C_];
__device__ __nv_bfloat16 g_Wph[C_*C_], g_Wpl[C_*C_];
__device__ __nv_bfloat16 g_Xh[M_*C_],  g_Xl[M_*C_];

// ============================================================================
// Generic fp32 -> bf16 hi/lo split (one float4 per thread)
// ============================================================================
__global__ __launch_bounds__(256)
void v_split(const float* __restrict__ v, __nv_bfloat16* __restrict__ oh,
             __nv_bfloat16* __restrict__ ol)
{
    int i = blockIdx.x * blockDim.x + threadIdx.x;
    float4 x = ((const float4*)v)[i];
    __nv_bfloat16 h0,l0,h1,l1,h2,l2,h3,l3;
    bsplit(x.x, h0, l0); bsplit(x.y, h1, l1);
    bsplit(x.z, h2, l2); bsplit(x.w, h3, l3);
    ((u32*)oh)[2*i]   = pack_bf(h0, h1);
    ((u32*)oh)[2*i+1] = pack_bf(h2, h3);
    ((u32*)ol)[2*i]   = pack_bf(l0, l1);
    ((u32*)ol)[2*i+1] = pack_bf(l2, l3);
}

// ============================================================================
// Split-bf16 tensor-core GEMM: out[M,N] = A @ W, M=4096, N=K=1024.
// CTA tile 128x128, 8 warps (4m x 2n), warp 32x64, K-chunk 32, cp.async x2.
// EPI=0: row-major fp32. EPI=1: head-split [B,H,L,64].
// Smem: A hi/lo [128][56], W hi/lo [32][152]; per-stage 48128 B, 2 stages.
// ============================================================================
#define GS_AH 0
#define GS_AL 14336
#define GS_WH 28672
#define GS_WL 38400
#define GS_STAGE 48128
#define GS_TOTAL (2*GS_STAGE)

template<int EPI>
__device__ __forceinline__
void gemm_tc_body(const __nv_bfloat16* __restrict__ Ah, const __nv_bfloat16* __restrict__ Al,
                  const __nv_bfloat16* __restrict__ Wh, const __nv_bfloat16* __restrict__ Wl,
                  float* __restrict__ out, int L)
{
    extern __shared__ char gsm[];
    const u32 dynu = smem_u32(gsm);
    const int tid = threadIdx.x;
    const int wid = tid >> 5, lane = tid & 31;
    const int wm = wid >> 1, wn = wid & 1;
    const int m0 = blockIdx.y * 128, n0 = blockIdx.x * 128;

    // stage loader: chunk kc into stage s
    auto load_stage = [&](int s, int kc) {
        u32 sb = dynu + s * GS_STAGE;
        #pragma unroll
        for (int i = tid; i < 512; i += 256) {
            int r = i >> 2, c = i & 3;    // A: 128 rows x 4 chunks (32 bf16/row)
            u32 off = (u32)(r * 56 + c * 8) * 2;
            const __nv_bfloat16* sa = Ah + (size_t)(m0 + r) * C_ + kc * 32 + c * 8;
            const __nv_bfloat16* sl = Al + (size_t)(m0 + r) * C_ + kc * 32 + c * 8;
            cpa16(sb + GS_AH + off, sa);
            cpa16(sb + GS_AL + off, sl);
        }
        #pragma unroll
        for (int i = tid; i < 512; i += 256) {
            int r = i >> 4, c = i & 15;   // W: 32 rows x 16 chunks (128 bf16/row)
            u32 off = (u32)(r * 152 + c * 8) * 2;
            const __nv_bfloat16* sw = Wh + (size_t)(kc * 32 + r) * C_ + n0 + c * 8;
            const __nv_bfloat16* sl = Wl + (size_t)(kc * 32 + r) * C_ + n0 + c * 8;
            cpa16(sb + GS_WH + off, sw);
            cpa16(sb + GS_WL + off, sl);
        }
    };

    float acc[2][8][4];
    #pragma unroll
    for (int mt = 0; mt < 2; mt++)
        #pragma unroll
        for (int nn = 0; nn < 8; nn++)
            #pragma unroll
            for (int p = 0; p < 4; p++) acc[mt][nn][p] = 0.f;

    load_stage(0, 0); CPA_COMMIT();
    load_stage(1, 1); CPA_COMMIT();

    const u32 aLane = (u32)((lane & 15) * 56 + ((lane >> 4) << 3)) * 2;
    const u32 wLane = (u32)((lane & 15) * 152) * 2;

    for (int kc = 0; kc < 32; kc++) {
        int s = kc & 1;
        CPA_WAIT1();
        __syncthreads();

        u32 sb = dynu + s * GS_STAGE;
        u32 ah[2][2][4], al[2][2][4];
        #pragma unroll
        for (int mt = 0; mt < 2; mt++)
            #pragma unroll
            for (int kk = 0; kk < 2; kk++) {
                u32 off = (u32)((wm * 32 + mt * 16) * 56 + kk * 16) * 2 + aLane;
                ldsm_x4(ah[mt][kk], sb + GS_AH + off);
                ldsm_x4(al[mt][kk], sb + GS_AL + off);
            }
        #pragma unroll
        for (int kk = 0; kk < 2; kk++)
            #pragma unroll
            for (int nn = 0; nn < 8; nn++) {
                u32 off = (u32)(kk * 16 * 152 + wn * 64 + nn * 8) * 2 + wLane;
                u32 bh0, bh1, bl0, bl1;
                ldsm_x2t(bh0, bh1, sb + GS_WH + off);
                ldsm_x2t(bl0, bl1, sb + GS_WL + off);
                #pragma unroll
                for (int mt = 0; mt < 2; mt++) {
                    mma_bf16(acc[mt][nn], ah[mt][kk], bh0, bh1);
                    mma_bf16(acc[mt][nn], ah[mt][kk], bl0, bl1);
                    mma_bf16(acc[mt][nn], al[mt][kk], bh0, bh1);
                }
            }

        __syncthreads();
        if (kc + 2 < 32) load_stage(s, kc + 2);
        CPA_COMMIT();
    }

    // epilogue
    const int g = lane >> 2, tig = lane & 3;
    #pragma unroll
    for (int mt = 0; mt < 2; mt++) {
        int row = m0 + wm * 32 + mt * 16 + g;
        #pragma unroll
        for (int nn = 0; nn < 8; nn++) {
            int n = n0 + wn * 64 + nn * 8 + 2 * tig;
            if (EPI == 0) {
                *(float2*)(out + (size_t)row * C_ + n) =
                    make_float2(acc[mt][nn][0], acc[mt][nn][1]);
                *(float2*)(out + (size_t)(row + 8) * C_ + n) =
                    make_float2(acc[mt][nn][2], acc[mt][nn][3]);
            } else {
                int hh = n >> 6, d = n & 63;
                int b0r = row / L, l0r = row % L;
                int b1r = (row + 8) / L, l1r = (row + 8) % L;
                *(float2*)(out + (((size_t)(b0r * H_ + hh) * L + l0r) << 6) + d) =
                    make_float2(acc[mt][nn][0], acc[mt][nn][1]);
                *(float2*)(out + (((size_t)(b1r * H_ + hh) * L + l1r) << 6) + d) =
                    make_float2(acc[mt][nn][2], acc[mt][nn][3]);
            }
        }
    }
}

__global__ __launch_bounds__(256)
void gemm3_bf16(float* __restrict__ Q, float* __restrict__ K, float* __restrict__ V)
{
    int z = blockIdx.z;
    const __nv_bfloat16 *Ah, *Al, *Wh, *Wl;
    float* O;
    if (z == 0)      { Ah = g_Iqh; Al = g_Iql; Wh = g_Wqh; Wl = g_Wql; O = Q; }
    else if (z == 1) { Ah = g_Ikh; Al = g_Ikl; Wh = g_Wkh; Wl = g_Wkl; O = K; }
    else             { Ah = g_Ivh; Al = g_Ivl; Wh = g_Wvh; Wl = g_Wvl; O = V; }
    gemm_tc_body<1>(Ah, Al, Wh, Wl, O, NQ);
}
__global__ __launch_bounds__(256)
void gemm1_bf16(float* __restrict__ out)
{
    gemm_tc_body<0>(g_Xh, g_Xl, g_Wph, g_Wpl, out, NQ);
}

// ============================================================================
// RoPE + bf16 hi/lo split
// ============================================================================
__global__ __launch_bounds__(256)
void rope_convert(const float* __restrict__ t, __nv_bfloat16* __restrict__ oh,
                  __nv_bfloat16* __restrict__ ol, const float* __restrict__ pos,
                  float scale, int L)
{
    int idx = blockIdx.x * blockDim.x + threadIdx.x;
    int pair = idx & 31, row = idx >> 5, l = row & (L - 1);
    const float* p = t + (size_t)row * 64;
    float x1 = p[pair], x2 = p[pair + 32];
    float s1, c1, s2, c2;
    sincosf(pos[l * 64 + pair], &s1, &c1);
    sincosf(pos[l * 64 + pair + 32], &s2, &c2);
    float y1 = scale * (x1 * c1 - x2 * s1);
    float y2 = scale * (x2 * c2 + x1 * s2);
    __nv_bfloat16 h, lo;
    bsplit(y1, h, lo);
    oh[(size_t)row*64 + pair] = h;  ol[(size_t)row*64 + pair] = lo;
    bsplit(y2, h, lo);
    oh[(size_t)row*64 + pair + 32] = h;  ol[(size_t)row*64 + pair + 32] = lo;
}

// ============================================================================
// Flash attention with mma.sync bf16 (unchanged from R5 — passed)
// ============================================================================
#define ROWP 72

__global__ __launch_bounds__(128)
void attn_mma(const int* __restrict__ mask,
              const __nv_bfloat16* __restrict__ Qh, const __nv_bfloat16* __restrict__ Ql,
              const __nv_bfloat16* __restrict__ Kh, const __nv_bfloat16* __restrict__ Kl,
              const __nv_bfloat16* __restrict__ Vh, const __nv_bfloat16* __restrict__ Vl,
              float* __restrict__ X)
{
    __shared__ __nv_bfloat16 sKh[64][ROWP], sKl[64][ROWP];
    __shared__ __nv_bfloat16 sVh[64][ROWP], sVl[64][ROWP];
    __shared__ int s_mask[64];

    const int tid  = threadIdx.x;
    const int wid  = tid >> 5, lane = tid & 31;
    const int g    = lane >> 2, tig = lane & 3;
    const int bh   = blockIdx.x, b = bh >> 4, h = bh & 15;
    const int q0   = blockIdx.y * 64;
    const int r0   = wid * 16;

    const u32 baseKh = smem_u32(&sKh[0][0]);
    const u32 baseKl = smem_u32(&sKl[0][0]);
    const u32 baseVh = smem_u32(&sVh[0][0]);
    const u32 baseVl = smem_u32(&sVl[0][0]);

    {
        const __nv_bfloat16* qh = Qh + ((size_t)bh * NQ + q0) * HD;
        const __nv_bfloat16* ql = Ql + ((size_t)bh * NQ + q0) * HD;
        for (int i = tid; i < 512; i += 128) {
            int row = i >> 3, c8 = i & 7;
            *(float4*)(&sKh[row][c8*8]) = *(const float4*)(qh + row*64 + c8*8);
            *(float4*)(&sKl[row][c8*8]) = *(const float4*)(ql + row*64 + c8*8);
        }
    }
    __syncthreads();

    u32 qh[4][4], ql[4][4];
    {
        u32 rowoff = (u32)((r0 + (lane & 15)) * ROWP + ((lane >> 4) << 3)) * 2;
        #pragma unroll
        for (int kk = 0; kk < 4; kk++) {
            ldsm_x4(qh[kk], baseKh + rowoff + kk * 32);
            ldsm_x4(ql[kk], baseKl + rowoff + kk * 32);
        }
    }

    float oacc[8][4];
    #pragma unroll
    for (int nn = 0; nn < 8; nn++)
        #pragma unroll
        for (int p = 0; p < 4; p++) oacc[nn][p] = 0.f;
    float lacc0 = 0.f, lacc1 = 0.f;

    const u32 kAddrLane = (u32)((lane & 7) * ROWP + ((lane >> 3) & 1) * 8) * 2;
    const u32 vAddrLane = (u32)((lane & 15) * ROWP) * 2;

    for (int t = 0; t < NKV / 64; t++) {
        __syncthreads();
        {
            const __nv_bfloat16* kh = Kh + ((size_t)bh * NKV + t*64) * HD;
            const __nv_bfloat16* kl = Kl + ((size_t)bh * NKV + t*64) * HD;
            const __nv_bfloat16* vh = Vh + ((size_t)bh * NKV + t*64) * HD;
            const __nv_bfloat16* vl = Vl + ((size_t)bh * NKV + t*64) * HD;
            for (int i = tid; i < 512; i += 128) {
                int row = i >> 3, c8 = i & 7;
                *(float4*)(&sKh[row][c8*8]) = *(const float4*)(kh + row*64 + c8*8);
                *(float4*)(&sKl[row][c8*8]) = *(const float4*)(kl + row*64 + c8*8);
                *(float4*)(&sVh[row][c8*8]) = *(const float4*)(vh + row*64 + c8*8);
                *(float4*)(&sVl[row][c8*8]) = *(const float4*)(vl + row*64 + c8*8);
            }
            if (tid < 64) s_mask[tid] = mask[b * NKV + t*64 + tid];
        }
        __syncthreads();

        float sacc[8][4];
        #pragma unroll
        for (int nn = 0; nn < 8; nn++)
            #pragma unroll
            for (int p = 0; p < 4; p++) sacc[nn][p] = 0.f;

        #pragma unroll
        for (int kk = 0; kk < 4; kk++) {
            #pragma unroll
            for (int nn = 0; nn < 8; nn++) {
                u32 off = kAddrLane + (u32)(nn * 8 * ROWP + kk * 16) * 2;
                u32 bh0, bh1, bl0, bl1;
                ldsm_x2(bh0, bh1, baseKh + off);
                ldsm_x2(bl0, bl1, baseKl + off);
                mma_bf16(sacc[nn], qh[kk], bh0, bh1);
                mma_bf16(sacc[nn], qh[kk], bl0, bl1);
                mma_bf16(sacc[nn], ql[kk], bh0, bh1);
            }
        }

        u32 ph[4][4], pl[4][4];
        #pragma unroll
        for (int nn = 0; nn < 8; nn++) {
            int m0 = s_mask[nn*8 + 2*tig], m1 = s_mask[nn*8 + 2*tig + 1];
            float p00 = m0 ? __expf(sacc[nn][0]) : 0.f;
            float p01 = m1 ? __expf(sacc[nn][1]) : 0.f;
            float p10 = m0 ? __expf(sacc[nn][2]) : 0.f;
            float p11 = m1 ? __expf(sacc[nn][3]) : 0.f;
            lacc0 += p00 + p01;
            lacc1 += p10 + p11;
            __nv_bfloat16 a, bb;
            int kk = nn >> 1, hi = nn & 1;
            bsplit(p00, a, bb); __nv_bfloat16 c, d; bsplit(p01, c, d);
            ph[kk][hi ? 2 : 0] = pack_bf(a, c);
            pl[kk][hi ? 2 : 0] = pack_bf(bb, d);
            bsplit(p10, a, bb); bsplit(p11, c, d);
            ph[kk][hi ? 3 : 1] = pack_bf(a, c);
            pl[kk][hi ? 3 : 1] = pack_bf(bb, d);
        }

        #pragma unroll
        for (int kk = 0; kk < 4; kk++) {
            #pragma unroll
            for (int nn = 0; nn < 8; nn++) {
                u32 off = vAddrLane + (u32)(kk * 16 * ROWP + nn * 8) * 2;
                u32 bh0, bh1, bl0, bl1;
                ldsm_x2t(bh0, bh1, baseVh + off);
                ldsm_x2t(bl0, bl1, baseVl + off);
                mma_bf16(oacc[nn], ph[kk], bh0, bh1);
                mma_bf16(oacc[nn], ph[kk], bl0, bl1);
                mma_bf16(oacc[nn], pl[kk], bh0, bh1);
            }
        }
    }

    lacc0 += __shfl_xor_sync(0xffffffffu, lacc0, 1);
    lacc0 += __shfl_xor_sync(0xffffffffu, lacc0, 2);
    lacc1 += __shfl_xor_sync(0xffffffffu, lacc1, 1);
    lacc1 += __shfl_xor_sync(0xffffffffu, lacc1, 2);
    float inv0 = 1.f / lacc0, inv1 = 1.f / lacc1;

    int row0 = q0 + r0 + g, row1 = row0 + 8;
    float* x0 = X + (size_t)(b * NQ + row0) * C_ + h * 64;
    float* x1 = X + (size_t)(b * NQ + row1) * C_ + h * 64;
    #pragma unroll
    for (int nn = 0; nn < 8; nn++) {
        int c = nn * 8 + 2 * tig;
        *(float2*)(x0 + c) = make_float2(oacc[nn][0] * inv0, oacc[nn][1] * inv0);
        *(float2*)(x1 + c) = make_float2(oacc[nn][2] * inv1, oacc[nn][3] * inv1);
    }
}

// ============================================================================
extern "C" void kernel_launch(void* const* d_in, const int* in_sizes, int n_in,
                              void* d_out, int out_size)
{
    const float* q    = (const float*)d_in[0];
    const float* k    = (const float*)d_in[1];
    const float* v    = (const float*)d_in[2];
    const int*   mask = (const int*)  d_in[3];
    const float* pos  = (const float*)d_in[4];
    const float* qW   = (const float*)d_in[5];
    const float* kW   = (const float*)d_in[6];
    const float* vW   = (const float*)d_in[7];
    const float* pW   = (const float*)d_in[8];
    float* out = (float*)d_out;

    float *Qp, *Kp, *Vp, *Xp;
    cudaGetSymbolAddress((void**)&Qp, g_Q);
    cudaGetSymbolAddress((void**)&Kp, g_K);
    cudaGetSymbolAddress((void**)&Vp, g_V);
    cudaGetSymbolAddress((void**)&Xp, g_X);
    __nv_bfloat16 *Qh, *Ql, *Kh, *Kl, *Vh, *Vl;
    cudaGetSymbolAddress((void**)&Qh, g_Qh);
    cudaGetSymbolAddress((void**)&Ql, g_Ql);
    cudaGetSymbolAddress((void**)&Kh, g_Kh);
    cudaGetSymbolAddress((void**)&Kl, g_Kl);
    cudaGetSymbolAddress((void**)&Vh, g_Vh);
    cudaGetSymbolAddress((void**)&Vl, g_Vl);
    __nv_bfloat16 *Iqh, *Iql, *Ikh, *Ikl, *Ivh, *Ivl;
    cudaGetSymbolAddress((void**)&Iqh, g_Iqh);
    cudaGetSymbolAddress((void**)&Iql, g_Iql);
    cudaGetSymbolAddress((void**)&Ikh, g_Ikh);
    cudaGetSymbolAddress((void**)&Ikl, g_Ikl);
    cudaGetSymbolAddress((void**)&Ivh, g_Ivh);
    cudaGetSymbolAddress((void**)&Ivl, g_Ivl);
    __nv_bfloat16 *Wqh, *Wql, *Wkh, *Wkl, *Wvh, *Wvl, *Wph, *Wpl, *Xh, *Xl;
    cudaGetSymbolAddress((void**)&Wqh, g_Wqh);
    cudaGetSymbolAddress((void**)&Wql, g_Wql);
    cudaGetSymbolAddress((void**)&Wkh, g_Wkh);
    cudaGetSymbolAddress((void**)&Wkl, g_Wkl);
    cudaGetSymbolAddress((void**)&Wvh, g_Wvh);
    cudaGetSymbolAddress((void**)&Wvl, g_Wvl);
    cudaGetSymbolAddress((void**)&Wph, g_Wph);
    cudaGetSymbolAddress((void**)&Wpl, g_Wpl);
    cudaGetSymbolAddress((void**)&Xh, g_Xh);
    cudaGetSymbolAddress((void**)&Xl, g_Xl);

    cudaFuncSetAttribute(gemm3_bf16, cudaFuncAttributeMaxDynamicSharedMemorySize, GS_TOTAL);
    cudaFuncSetAttribute(gemm1_bf16, cudaFuncAttributeMaxDynamicSharedMemorySize, GS_TOTAL);

    // split inputs + weights
    const int BIG = (M_ * C_ / 4) / 256;   // 4096 blocks
    const int SML = (C_ * C_ / 4) / 256;   // 1024 blocks
    v_split<<<BIG, 256>>>(q, Iqh, Iql);
    v_split<<<BIG, 256>>>(k, Ikh, Ikl);
    v_split<<<BIG, 256>>>(v, Ivh, Ivl);
    v_split<<<SML, 256>>>(qW, Wqh, Wql);
    v_split<<<SML, 256>>>(kW, Wkh, Wkl);
    v_split<<<SML, 256>>>(vW, Wvh, Wvl);
    v_split<<<SML, 256>>>(pW, Wph, Wpl);

    // projections (tensor core)
    gemm3_bf16<<<dim3(C_/128, M_/128, 3), 256, GS_TOTAL>>>(Qp, Kp, Vp);

    // rope + splits
    int rb = (B_ * H_ * NQ * 32) / 256;
    rope_convert<<<rb, 256>>>(Qp, Qh, Ql, pos, 0.125f, NQ);
    rope_convert<<<rb, 256>>>(Kp, Kh, Kl, pos, 1.0f, NKV);
    v_split<<<BIG, 256>>>(Vp, Vh, Vl);

    // attention (tensor core)
    attn_mma<<<dim3(B_ * H_, NQ / 64), 128>>>(mask, Qh, Ql, Kh, Kl, Vh, Vl, Xp);

    // output projection (tensor core)
    v_split<<<BIG, 256>>>(Xp, Xh, Xl);
    gemm1_bf16<<<dim3(C_/128, M_/128, 1), 256, GS_TOTAL>>>(out);
}